// round 1
// baseline (speedup 1.0000x reference)
#include <cuda_runtime.h>
#include <cstdint>
#include <cstddef>

#define T_TOK 8192
#define DM    1024
#define NE    8

#define BM 128
#define BN 128
#define BK 32
#define LDA 36                    // padded smem row stride (floats): bank = 4*gid+tig, conflict-free
#define ABUF (BM*LDA)             // floats per A (or B) buffer = 4608
#define ABYTES (ABUF*4)           // 18432 bytes
#define SMEM_BYTES (4*ABUF*4 + BM*8)   // A x2 + B x2 + s_tok + s_w = 74752

// ---- static device scratch (no allocations allowed) ----
__device__ __align__(16) float g_x_tf[(size_t)T_TOK * DM];     // tf32-rounded x
__device__ __align__(16) float g_We_tf[(size_t)NE * DM * DM];  // tf32-rounded We
__device__ int   g_tok[NE * T_TOK];
__device__ float g_wgt[NE * T_TOK];
__device__ int   g_cnt[NE];

__device__ __forceinline__ float tf32_rn(float v) {
    uint32_t u;
    asm("cvt.rna.tf32.f32 %0, %1;" : "=r"(u) : "f"(v));
    return __uint_as_float(u);
}

__device__ __forceinline__ void cp16(uint32_t dst, const void* src) {
    asm volatile("cp.async.cg.shared.global [%0], [%1], 16;" :: "r"(dst), "l"(src) : "memory");
}

// ---- kernel 1: round We to tf32, zero output, zero counters ----
__global__ void prep_kernel(const float4* __restrict__ We, float4* __restrict__ out) {
    int i = blockIdx.x * blockDim.x + threadIdx.x;   // i < 2097152
    float4 w = We[i];
    float4 r;
    r.x = tf32_rn(w.x); r.y = tf32_rn(w.y); r.z = tf32_rn(w.z); r.w = tf32_rn(w.w);
    reinterpret_cast<float4*>(g_We_tf)[i] = r;
    out[i] = make_float4(0.f, 0.f, 0.f, 0.f);
    if (i < NE) g_cnt[i] = 0;
}

// ---- kernel 2: gating (1 warp / token) + write tf32-rounded x ----
__global__ void gate_kernel(const float* __restrict__ x, const float* __restrict__ Wg,
                            const float* __restrict__ bg) {
    int t = blockIdx.x * 8 + (threadIdx.x >> 5);
    int lane = threadIdx.x & 31;
    const float* xr = x + (size_t)t * DM;

    float acc[NE];
#pragma unroll
    for (int e = 0; e < NE; e++) acc[e] = 0.f;

    for (int d = lane; d < DM; d += 32) {
        float v = xr[d];
        g_x_tf[(size_t)t * DM + d] = tf32_rn(v);
#pragma unroll
        for (int e = 0; e < NE; e++) acc[e] = fmaf(v, Wg[e * DM + d], acc[e]);
    }
#pragma unroll
    for (int e = 0; e < NE; e++) {
#pragma unroll
        for (int o = 16; o > 0; o >>= 1) acc[e] += __shfl_xor_sync(0xffffffffu, acc[e], o);
    }

    if (lane == 0) {
        float l[NE];
        float m = -1e30f;
#pragma unroll
        for (int e = 0; e < NE; e++) { l[e] = acc[e] + bg[e]; m = fmaxf(m, l[e]); }
        float p[NE];
        float s = 0.f;
#pragma unroll
        for (int e = 0; e < NE; e++) { p[e] = expf(l[e] - m); s += p[e]; }
        // top-2 on logits (monotone with softmax); ties -> first occurrence (matches lax.top_k)
        int e0 = 0;
#pragma unroll
        for (int e = 1; e < NE; e++) if (l[e] > l[e0]) e0 = e;
        int e1 = (e0 == 0) ? 1 : 0;
#pragma unroll
        for (int e = 0; e < NE; e++) if (e != e0 && l[e] > l[e1]) e1 = e;
        float inv = 1.f / s;

        int q0 = atomicAdd(&g_cnt[e0], 1);
        g_tok[e0 * T_TOK + q0] = t;
        g_wgt[e0 * T_TOK + q0] = p[e0] * inv;
        int q1 = atomicAdd(&g_cnt[e1], 1);
        g_tok[e1 * T_TOK + q1] = t;
        g_wgt[e1 * T_TOK + q1] = p[e1] * inv;
    }
}

// ---- kernel 3: gathered per-expert GEMM, tf32 mma.sync, atomicAdd combine ----
__global__ void __launch_bounds__(256)
moe_gemm_kernel(const float* __restrict__ be, float* __restrict__ out) {
    const int e = blockIdx.z;
    const int cnt = g_cnt[e];
    const int m0 = blockIdx.x * BM;
    if (m0 >= cnt) return;

    extern __shared__ __align__(16) char sm_raw[];
    float* As = (float*)sm_raw;                          // 2 * ABUF floats
    float* Bs = As + 2 * ABUF;                           // 2 * ABUF floats
    int*   s_tok = (int*)(sm_raw + (size_t)4 * ABUF * 4);
    float* s_w   = (float*)(sm_raw + (size_t)4 * ABUF * 4 + BM * 4);

    const int tid = threadIdx.x;

    if (tid < BM) {
        int pos = m0 + tid;
        int tok = 0; float w = 0.f;
        if (pos < cnt) { tok = g_tok[e * T_TOK + pos]; w = g_wgt[e * T_TOK + pos]; }
        s_tok[tid] = tok; s_w[tid] = w;
    }
    __syncthreads();

    uint32_t sbase = (uint32_t)__cvta_generic_to_shared(sm_raw);
    const float* a_src[4];
    const float* b_src[4];
    uint32_t a_dst[4], b_dst[4];
#pragma unroll
    for (int i = 0; i < 4; i++) {
        int slot = i * 256 + tid;
        int row = slot >> 3, q = slot & 7;                    // 128 rows x 8 float4-quads
        a_src[i] = g_x_tf + (size_t)s_tok[row] * DM + q * 4;
        a_dst[i] = sbase + (uint32_t)(row * LDA + q * 4) * 4u;
        b_src[i] = g_We_tf + ((size_t)e * DM * DM) + (size_t)(blockIdx.y * BN + row) * DM + q * 4;
        b_dst[i] = sbase + (uint32_t)(2 * ABUF + row * LDA + q * 4) * 4u;
    }

    const int wid = tid >> 5, lane = tid & 31;
    const int wm = (wid & 1) * 64;      // warp tile: 64(M) x 32(N), warps 2x4
    const int wn = (wid >> 1) * 32;
    const int gid = lane >> 2, tig = lane & 3;

    float acc[4][4][4];
#pragma unroll
    for (int i0 = 0; i0 < 4; i0++)
#pragma unroll
        for (int i1 = 0; i1 < 4; i1++)
#pragma unroll
            for (int i2 = 0; i2 < 4; i2++) acc[i0][i1][i2] = 0.f;

    // prologue: chunk 0 -> buf 0
#pragma unroll
    for (int i = 0; i < 4; i++) cp16(a_dst[i], a_src[i]);
#pragma unroll
    for (int i = 0; i < 4; i++) cp16(b_dst[i], b_src[i]);
    asm volatile("cp.async.commit_group;" ::: "memory");

    const int NCH = DM / BK;   // 32
    for (int ch = 0; ch < NCH; ++ch) {
        int buf = ch & 1;
        if (ch + 1 < NCH) {
            int nb = buf ^ 1;
            int k0 = (ch + 1) * BK;
#pragma unroll
            for (int i = 0; i < 4; i++) cp16(a_dst[i] + nb * ABYTES, a_src[i] + k0);
#pragma unroll
            for (int i = 0; i < 4; i++) cp16(b_dst[i] + nb * ABYTES, b_src[i] + k0);
            asm volatile("cp.async.commit_group;" ::: "memory");
            asm volatile("cp.async.wait_group 1;" ::: "memory");
        } else {
            asm volatile("cp.async.wait_group 0;" ::: "memory");
        }
        __syncthreads();

        const float* Ab = As + buf * ABUF;
        const float* Bb = Bs + buf * ABUF;
#pragma unroll
        for (int ks = 0; ks < 4; ks++) {
            uint32_t af[4][4], bf[4][2];
#pragma unroll
            for (int ma = 0; ma < 4; ma++) {
                const float* p = Ab + (wm + ma * 16 + gid) * LDA + ks * 8 + tig;
                af[ma][0] = __float_as_uint(p[0]);
                af[ma][1] = __float_as_uint(p[8 * LDA]);
                af[ma][2] = __float_as_uint(p[4]);
                af[ma][3] = __float_as_uint(p[8 * LDA + 4]);
            }
#pragma unroll
            for (int na = 0; na < 4; na++) {
                const float* p = Bb + (wn + na * 8 + gid) * LDA + ks * 8 + tig;
                bf[na][0] = __float_as_uint(p[0]);
                bf[na][1] = __float_as_uint(p[4]);
            }
#pragma unroll
            for (int ma = 0; ma < 4; ma++)
#pragma unroll
                for (int na = 0; na < 4; na++) {
                    asm volatile(
                        "mma.sync.aligned.m16n8k8.row.col.f32.tf32.tf32.f32 "
                        "{%0,%1,%2,%3}, {%4,%5,%6,%7}, {%8,%9}, {%0,%1,%2,%3};"
                        : "+f"(acc[ma][na][0]), "+f"(acc[ma][na][1]),
                          "+f"(acc[ma][na][2]), "+f"(acc[ma][na][3])
                        : "r"(af[ma][0]), "r"(af[ma][1]), "r"(af[ma][2]), "r"(af[ma][3]),
                          "r"(bf[na][0]), "r"(bf[na][1]));
                }
        }
        __syncthreads();
    }

    // epilogue: out[t, j] += w * (acc + be[e, j])  (exactly 2 commutative adds per element)
    const float* be_e = be + e * DM;
    const int jb = blockIdx.y * BN + wn;
#pragma unroll
    for (int na = 0; na < 4; na++) {
        int j = jb + na * 8 + tig * 2;
        float bb0 = be_e[j], bb1 = be_e[j + 1];
#pragma unroll
        for (int ma = 0; ma < 4; ma++) {
            int r = wm + ma * 16 + gid;
            int t0 = s_tok[r];     float w0 = s_w[r];
            int t1 = s_tok[r + 8]; float w1 = s_w[r + 8];
            if (w0 != 0.f) {
                atomicAdd(out + (size_t)t0 * DM + j,     w0 * (acc[ma][na][0] + bb0));
                atomicAdd(out + (size_t)t0 * DM + j + 1, w0 * (acc[ma][na][1] + bb1));
            }
            if (w1 != 0.f) {
                atomicAdd(out + (size_t)t1 * DM + j,     w1 * (acc[ma][na][2] + bb0));
                atomicAdd(out + (size_t)t1 * DM + j + 1, w1 * (acc[ma][na][3] + bb1));
            }
        }
    }
}

extern "C" void kernel_launch(void* const* d_in, const int* in_sizes, int n_in,
                              void* d_out, int out_size) {
    const float* x  = (const float*)d_in[0];
    const float* Wg = (const float*)d_in[1];
    const float* bg = (const float*)d_in[2];
    const float* We = (const float*)d_in[3];
    const float* be = (const float*)d_in[4];
    float* out = (float*)d_out;
    (void)in_sizes; (void)n_in; (void)out_size;

    cudaFuncSetAttribute(moe_gemm_kernel,
                         cudaFuncAttributeMaxDynamicSharedMemorySize, SMEM_BYTES);

    prep_kernel<<<(T_TOK * DM / 4) / 256, 256>>>((const float4*)We, (float4*)out);
    gate_kernel<<<T_TOK / 8, 256>>>(x, Wg, bg);
    moe_gemm_kernel<<<dim3(T_TOK / BM, DM / BN, NE), 256, SMEM_BYTES>>>(be, out);
}

// round 3
// speedup vs baseline: 1.5783x; 1.5783x over previous
#include <cuda_runtime.h>
#include <cuda_fp16.h>
#include <cstdint>
#include <cstddef>

#define T_TOK 8192
#define DM    1024
#define NE    8

#define BM 128
#define BN 128
#define BK 32                    // halves of K per chunk
#define LDH 80                   // bytes per smem row (40 halves): conflict-free for ldmatrix
#define STAGE_B (BM*LDH)         // 10240 bytes per tile stage
#define A_OFF 1536
#define B_OFF (A_OFF + 2*STAGE_B)
#define SMEM_TOTAL (B_OFF + 2*STAGE_B)   // 42496

// ---- static device scratch (no allocations allowed) ----
__device__ __align__(16) __half g_x_h[(size_t)T_TOK * DM];     // fp16 x
__device__ __align__(16) __half g_We_h[(size_t)NE * DM * DM];  // fp16 We
__device__ int   g_tok[NE * T_TOK];
__device__ float g_wgt[NE * T_TOK];
__device__ int   g_cnt[NE];

__device__ __forceinline__ void cp16(uint32_t dst, const void* src) {
    asm volatile("cp.async.cg.shared.global [%0], [%1], 16;" :: "r"(dst), "l"(src) : "memory");
}

// ---- kernel 1: convert We to fp16, zero output, zero counters ----
__global__ void prep_kernel(const float4* __restrict__ We, float4* __restrict__ out) {
    int i = blockIdx.x * blockDim.x + threadIdx.x;   // i < 2097152 == NE*DM*DM/4
    float4 w = We[i];
    __half2 h0 = __floats2half2_rn(w.x, w.y);
    __half2 h1 = __floats2half2_rn(w.z, w.w);
    uint2 pk;
    pk.x = *reinterpret_cast<uint32_t*>(&h0);
    pk.y = *reinterpret_cast<uint32_t*>(&h1);
    reinterpret_cast<uint2*>(g_We_h)[i] = pk;
    out[i] = make_float4(0.f, 0.f, 0.f, 0.f);
    if (i < NE) g_cnt[i] = 0;
}

// ---- kernel 2: gating (1 warp / token) + write fp16 x ----
__global__ void gate_kernel(const float* __restrict__ x, const float* __restrict__ Wg,
                            const float* __restrict__ bg) {
    int t = blockIdx.x * 8 + (threadIdx.x >> 5);
    int lane = threadIdx.x & 31;
    const float* xr = x + (size_t)t * DM;

    float acc[NE];
#pragma unroll
    for (int e = 0; e < NE; e++) acc[e] = 0.f;

    for (int d = lane; d < DM; d += 32) {
        float v = xr[d];
        g_x_h[(size_t)t * DM + d] = __float2half_rn(v);
#pragma unroll
        for (int e = 0; e < NE; e++) acc[e] = fmaf(v, Wg[e * DM + d], acc[e]);
    }
#pragma unroll
    for (int e = 0; e < NE; e++) {
#pragma unroll
        for (int o = 16; o > 0; o >>= 1) acc[e] += __shfl_xor_sync(0xffffffffu, acc[e], o);
    }

    if (lane == 0) {
        float l[NE];
        float m = -1e30f;
#pragma unroll
        for (int e = 0; e < NE; e++) { l[e] = acc[e] + bg[e]; m = fmaxf(m, l[e]); }
        float p[NE];
        float s = 0.f;
#pragma unroll
        for (int e = 0; e < NE; e++) { p[e] = expf(l[e] - m); s += p[e]; }
        int e0 = 0;
#pragma unroll
        for (int e = 1; e < NE; e++) if (l[e] > l[e0]) e0 = e;
        int e1 = (e0 == 0) ? 1 : 0;
#pragma unroll
        for (int e = 0; e < NE; e++) if (e != e0 && l[e] > l[e1]) e1 = e;
        float inv = 1.f / s;

        int q0 = atomicAdd(&g_cnt[e0], 1);
        g_tok[e0 * T_TOK + q0] = t;
        g_wgt[e0 * T_TOK + q0] = p[e0] * inv;
        int q1 = atomicAdd(&g_cnt[e1], 1);
        g_tok[e1 * T_TOK + q1] = t;
        g_wgt[e1 * T_TOK + q1] = p[e1] * inv;
    }
}

// ---- kernel 3: gathered per-expert fp16 GEMM (mma.sync m16n8k16, fp32 acc) ----
__global__ void __launch_bounds__(256)
moe_gemm_kernel(const float* __restrict__ be, float* __restrict__ out) {
    const int e = blockIdx.z;
    const int cnt = g_cnt[e];
    const int m0 = blockIdx.x * BM;
    if (m0 >= cnt) return;

    __shared__ __align__(16) char sm[SMEM_TOTAL];
    int*   s_tok  = (int*)sm;              // 128 ints
    float* s_w    = (float*)(sm + 512);    // 128 floats
    float* s_bias = (float*)(sm + 1024);   // 128 floats

    const int tid = threadIdx.x;
    const int n0 = blockIdx.y * BN;

    if (tid < BM) {
        int pos = m0 + tid;
        int tok = 0; float w = 0.f;
        if (pos < cnt) { tok = g_tok[e * T_TOK + pos]; w = g_wgt[e * T_TOK + pos]; }
        s_tok[tid] = tok; s_w[tid] = w;
        s_bias[tid] = be[e * DM + n0 + tid];
    }
    __syncthreads();

    const uint32_t sbase = (uint32_t)__cvta_generic_to_shared(sm);

    // cp.async mapping: per chunk, 512 A granules + 512 B granules (16B each)
    const __half* a_src[2];
    const __half* b_src[2];
    uint32_t a_dst[2], b_dst[2];
#pragma unroll
    for (int i = 0; i < 2; i++) {
        int slot = i * 256 + tid;
        int row = slot >> 2, q = slot & 3;            // 128 rows x 4 granules (64B/row)
        a_src[i] = g_x_h + (size_t)s_tok[row] * DM + q * 8;
        a_dst[i] = sbase + A_OFF + (uint32_t)(row * LDH + q * 16);
        b_src[i] = g_We_h + (size_t)e * DM * DM + (size_t)(n0 + row) * DM + q * 8;
        b_dst[i] = sbase + B_OFF + (uint32_t)(row * LDH + q * 16);
    }

    const int wid = tid >> 5, lane = tid & 31;
    const int wm = (wid & 1) * 64;       // warps 2 (M) x 4 (N): warp tile 64x32
    const int wn = (wid >> 1) * 32;
    const int gid = lane >> 2, tig = lane & 3;

    float acc[4][4][4];
#pragma unroll
    for (int i0 = 0; i0 < 4; i0++)
#pragma unroll
        for (int i1 = 0; i1 < 4; i1++)
#pragma unroll
            for (int i2 = 0; i2 < 4; i2++) acc[i0][i1][i2] = 0.f;

    // ldmatrix lane addressing (within-tile byte offsets)
    // A (m16k16 frag): row = lane&15, col halves = (lane>>4)*8
    const uint32_t a_lm = (uint32_t)((lane & 15) * LDH + (lane >> 4) * 16);
    // B (two n8k16 frags per x4): g=lane>>3: n = (g>>1)*8 + (lane&7), k halves = (g&1)*8
    const uint32_t b_lm = (uint32_t)(((((lane >> 3) >> 1) * 8) + (lane & 7)) * LDH
                                     + ((lane >> 3) & 1) * 16);

    // prologue: chunk 0 -> buf 0
#pragma unroll
    for (int i = 0; i < 2; i++) cp16(a_dst[i], a_src[i]);
#pragma unroll
    for (int i = 0; i < 2; i++) cp16(b_dst[i], b_src[i]);
    asm volatile("cp.async.commit_group;" ::: "memory");

    const int NCH = DM / BK;   // 32
    for (int ch = 0; ch < NCH; ++ch) {
        int buf = ch & 1;
        if (ch + 1 < NCH) {
            int nb = buf ^ 1;
            int k0 = (ch + 1) * BK;
#pragma unroll
            for (int i = 0; i < 2; i++) cp16(a_dst[i] + nb * STAGE_B, a_src[i] + k0);
#pragma unroll
            for (int i = 0; i < 2; i++) cp16(b_dst[i] + nb * STAGE_B, b_src[i] + k0);
            asm volatile("cp.async.commit_group;" ::: "memory");
            asm volatile("cp.async.wait_group 1;" ::: "memory");
        } else {
            asm volatile("cp.async.wait_group 0;" ::: "memory");
        }
        __syncthreads();

        const uint32_t Ab = sbase + A_OFF + buf * STAGE_B;
        const uint32_t Bb = sbase + B_OFF + buf * STAGE_B;
#pragma unroll
        for (int ks = 0; ks < 2; ks++) {
            uint32_t af[4][4];
#pragma unroll
            for (int ma = 0; ma < 4; ma++) {
                uint32_t addr = Ab + a_lm + (uint32_t)((wm + ma * 16) * LDH + ks * 32);
                asm volatile("ldmatrix.sync.aligned.m8n8.x4.shared.b16 {%0,%1,%2,%3}, [%4];"
                             : "=r"(af[ma][0]), "=r"(af[ma][1]), "=r"(af[ma][2]), "=r"(af[ma][3])
                             : "r"(addr));
            }
            uint32_t bf[2][4];
#pragma unroll
            for (int nb2 = 0; nb2 < 2; nb2++) {
                uint32_t addr = Bb + b_lm + (uint32_t)((wn + nb2 * 16) * LDH + ks * 32);
                asm volatile("ldmatrix.sync.aligned.m8n8.x4.shared.b16 {%0,%1,%2,%3}, [%4];"
                             : "=r"(bf[nb2][0]), "=r"(bf[nb2][1]), "=r"(bf[nb2][2]), "=r"(bf[nb2][3])
                             : "r"(addr));
            }
#pragma unroll
            for (int ma = 0; ma < 4; ma++)
#pragma unroll
                for (int na = 0; na < 4; na++) {
                    uint32_t b0 = bf[na >> 1][(na & 1) * 2];
                    uint32_t b1 = bf[na >> 1][(na & 1) * 2 + 1];
                    asm volatile(
                        "mma.sync.aligned.m16n8k16.row.col.f32.f16.f16.f32 "
                        "{%0,%1,%2,%3}, {%4,%5,%6,%7}, {%8,%9}, {%0,%1,%2,%3};"
                        : "+f"(acc[ma][na][0]), "+f"(acc[ma][na][1]),
                          "+f"(acc[ma][na][2]), "+f"(acc[ma][na][3])
                        : "r"(af[ma][0]), "r"(af[ma][1]), "r"(af[ma][2]), "r"(af[ma][3]),
                          "r"(b0), "r"(b1));
                }
        }
        __syncthreads();
    }

    // ---- epilogue: pair-shuffle to 4 consecutive cols, one red.v4 per (ma,na) ----
    const bool odd = (tig & 1);
#pragma unroll
    for (int ma = 0; ma < 4; ma++) {
        int r = wm + ma * 16 + gid;
        int rr = odd ? r + 8 : r;
        int tok = s_tok[rr];
        float w = s_w[rr];
        float* orow = out + (size_t)tok * DM + n0;
#pragma unroll
        for (int na = 0; na < 4; na++) {
            float v0 = acc[ma][na][0], v1 = acc[ma][na][1];
            float v2 = acc[ma][na][2], v3 = acc[ma][na][3];
            float u0 = __shfl_xor_sync(0xffffffffu, v0, 1);
            float u1 = __shfl_xor_sync(0xffffffffu, v1, 1);
            float u2 = __shfl_xor_sync(0xffffffffu, v2, 1);
            float u3 = __shfl_xor_sync(0xffffffffu, v3, 1);
            float r0, r1, r2, r3;
            if (!odd) { r0 = v0; r1 = v1; r2 = u0; r3 = u1; }   // row r,   cols j4..j4+3
            else      { r0 = u2; r1 = u3; r2 = v2; r3 = v3; }   // row r+8, cols j4..j4+3
            int j4 = wn + na * 8 + (tig >> 1) * 4;
            if (w != 0.f) {
                float o0 = w * (r0 + s_bias[j4 + 0]);
                float o1 = w * (r1 + s_bias[j4 + 1]);
                float o2 = w * (r2 + s_bias[j4 + 2]);
                float o3 = w * (r3 + s_bias[j4 + 3]);
                asm volatile("red.global.add.v4.f32 [%0], {%1,%2,%3,%4};"
                             :: "l"(orow + j4), "f"(o0), "f"(o1), "f"(o2), "f"(o3)
                             : "memory");
            }
        }
    }
}

extern "C" void kernel_launch(void* const* d_in, const int* in_sizes, int n_in,
                              void* d_out, int out_size) {
    const float* x  = (const float*)d_in[0];
    const float* Wg = (const float*)d_in[1];
    const float* bg = (const float*)d_in[2];
    const float* We = (const float*)d_in[3];
    const float* be = (const float*)d_in[4];
    float* out = (float*)d_out;
    (void)in_sizes; (void)n_in; (void)out_size;

    prep_kernel<<<(NE * DM * DM / 4) / 256, 256>>>((const float4*)We, (float4*)out);
    gate_kernel<<<T_TOK / 8, 256>>>(x, Wg, bg);
    moe_gemm_kernel<<<dim3(T_TOK / BM, DM / BN, NE), 256>>>(be, out);
}

// round 4
// speedup vs baseline: 1.6688x; 1.0574x over previous
#include <cuda_runtime.h>
#include <cuda_fp16.h>
#include <cstdint>
#include <cstddef>

#define T_TOK 8192
#define DM    1024
#define NE    8

#define BM 128
#define BN 256
#define CHUNK 64                  // halves of K per chunk (=128 B/row)
#define NCH (DM/CHUNK)            // 16
#define ABYTES (BM*128)           // 16384 per A stage
#define BBYTES (BN*128)           // 32768 per B stage
#define A_OFF 2048
#define B_OFF (A_OFF + 3*ABYTES)              // 51200
#define SMEM_TOTAL (B_OFF + 3*BBYTES)         // 149504

// ---- static device scratch (no allocations allowed) ----
__device__ __align__(16) __half g_x_h[(size_t)T_TOK * DM];     // fp16 x
__device__ __align__(16) __half g_We_h[(size_t)NE * DM * DM];  // fp16 We
__device__ int   g_tok[NE * T_TOK];
__device__ float g_wgt[NE * T_TOK];
__device__ int   g_cnt[NE];

__device__ __forceinline__ void cp16(uint32_t dst, const void* src) {
    asm volatile("cp.async.cg.shared.global [%0], [%1], 16;" :: "r"(dst), "l"(src) : "memory");
}

// ---- kernel 1: convert We to fp16, zero output, zero counters ----
__global__ void prep_kernel(const float4* __restrict__ We, float4* __restrict__ out) {
    int i = blockIdx.x * blockDim.x + threadIdx.x;   // i < NE*DM*DM/4
    float4 w = We[i];
    __half2 h0 = __floats2half2_rn(w.x, w.y);
    __half2 h1 = __floats2half2_rn(w.z, w.w);
    uint2 pk;
    pk.x = *reinterpret_cast<uint32_t*>(&h0);
    pk.y = *reinterpret_cast<uint32_t*>(&h1);
    reinterpret_cast<uint2*>(g_We_h)[i] = pk;
    out[i] = make_float4(0.f, 0.f, 0.f, 0.f);
    if (i < NE) g_cnt[i] = 0;
}

// ---- kernel 2: gating (1 warp / token) + write fp16 x ----
__global__ void gate_kernel(const float* __restrict__ x, const float* __restrict__ Wg,
                            const float* __restrict__ bg) {
    int t = blockIdx.x * 8 + (threadIdx.x >> 5);
    int lane = threadIdx.x & 31;
    const float* xr = x + (size_t)t * DM;

    float acc[NE];
#pragma unroll
    for (int e = 0; e < NE; e++) acc[e] = 0.f;

    for (int d = lane; d < DM; d += 32) {
        float v = xr[d];
        g_x_h[(size_t)t * DM + d] = __float2half_rn(v);
#pragma unroll
        for (int e = 0; e < NE; e++) acc[e] = fmaf(v, Wg[e * DM + d], acc[e]);
    }
#pragma unroll
    for (int e = 0; e < NE; e++) {
#pragma unroll
        for (int o = 16; o > 0; o >>= 1) acc[e] += __shfl_xor_sync(0xffffffffu, acc[e], o);
    }

    if (lane == 0) {
        float l[NE];
        float m = -1e30f;
#pragma unroll
        for (int e = 0; e < NE; e++) { l[e] = acc[e] + bg[e]; m = fmaxf(m, l[e]); }
        float p[NE];
        float s = 0.f;
#pragma unroll
        for (int e = 0; e < NE; e++) { p[e] = expf(l[e] - m); s += p[e]; }
        int e0 = 0;
#pragma unroll
        for (int e = 1; e < NE; e++) if (l[e] > l[e0]) e0 = e;
        int e1 = (e0 == 0) ? 1 : 0;
#pragma unroll
        for (int e = 0; e < NE; e++) if (e != e0 && l[e] > l[e1]) e1 = e;
        float inv = 1.f / s;

        int q0 = atomicAdd(&g_cnt[e0], 1);
        g_tok[e0 * T_TOK + q0] = t;
        g_wgt[e0 * T_TOK + q0] = p[e0] * inv;
        int q1 = atomicAdd(&g_cnt[e1], 1);
        g_tok[e1 * T_TOK + q1] = t;
        g_wgt[e1 * T_TOK + q1] = p[e1] * inv;
    }
}

// ---- kernel 3: gathered per-expert fp16 GEMM (mma.sync m16n8k16, fp32 acc) ----
// CTA tile 128x256, 8 warps (2M x 4N), warp tile 64x64, SW128-swizzled smem.
__global__ void __launch_bounds__(256, 1)
moe_gemm_kernel(const float* __restrict__ be, float* __restrict__ out) {
    const int e = blockIdx.z;
    const int cnt = g_cnt[e];
    const int m0 = blockIdx.x * BM;
    if (m0 >= cnt) return;

    extern __shared__ __align__(1024) char sm[];
    int*   s_tok  = (int*)sm;              // 128 ints
    float* s_w    = (float*)(sm + 512);    // 128 floats
    float* s_bias = (float*)(sm + 1024);   // 256 floats

    const int tid = threadIdx.x;
    const int n0 = blockIdx.y * BN;

    if (tid < BM) {
        int pos = m0 + tid;
        int tok = 0; float w = 0.f;
        if (pos < cnt) { tok = g_tok[e * T_TOK + pos]; w = g_wgt[e * T_TOK + pos]; }
        s_tok[tid] = tok; s_w[tid] = w;
    }
    s_bias[tid] = be[e * DM + n0 + tid];
    __syncthreads();

    const uint32_t sbase = (uint32_t)__cvta_generic_to_shared(sm);

    // cp.async mapping (per chunk): A = 1024 granules (4/thread), B = 2048 (8/thread)
    const __half* a_src[4];
    uint32_t a_dst[4];
#pragma unroll
    for (int i = 0; i < 4; i++) {
        int slot = i * 256 + tid;
        int row = slot >> 3, q = slot & 7;            // 128 rows x 8 granules
        a_src[i] = g_x_h + (size_t)s_tok[row] * DM + q * 8;
        a_dst[i] = sbase + A_OFF + (uint32_t)(row * 128 + ((q ^ (row & 7)) << 4));
    }
    const __half* b_src[8];
    uint32_t b_dst[8];
#pragma unroll
    for (int i = 0; i < 8; i++) {
        int slot = i * 256 + tid;
        int row = slot >> 3, q = slot & 7;            // 256 rows x 8 granules
        b_src[i] = g_We_h + (size_t)e * DM * DM + (size_t)(n0 + row) * DM + q * 8;
        b_dst[i] = sbase + B_OFF + (uint32_t)(row * 128 + ((q ^ (row & 7)) << 4));
    }

    const int wid = tid >> 5, lane = tid & 31;
    const int wm = (wid & 1) * 64;        // 2 M-warps
    const int wn = (wid >> 1) * 64;       // 4 N-warps
    const int gid = lane >> 2, tig = lane & 3;
    const uint32_t cmask = (uint32_t)((lane & 7) << 4);   // swizzle XOR (bits 4-6)

    // ldmatrix per-lane row/col components
    const uint32_t a_row = (uint32_t)(lane & 15);          // + wm + ma*16
    const uint32_t a_chi = (uint32_t)((lane >> 4) << 4);   // + ks*32
    const uint32_t b_row = (uint32_t)(((lane >> 4) << 3) + (lane & 7));  // + wn + nb*16
    const uint32_t b_chi = (uint32_t)(((lane >> 3) & 1) << 4);           // + ks*32

    float acc[4][8][4];
#pragma unroll
    for (int i0 = 0; i0 < 4; i0++)
#pragma unroll
        for (int i1 = 0; i1 < 8; i1++)
#pragma unroll
            for (int i2 = 0; i2 < 4; i2++) acc[i0][i1][i2] = 0.f;

    // prologue: chunks 0,1 -> stages 0,1
#pragma unroll
    for (int ch = 0; ch < 2; ch++) {
        int k0 = ch * CHUNK;
#pragma unroll
        for (int i = 0; i < 4; i++) cp16(a_dst[i] + ch * ABYTES, a_src[i] + k0);
#pragma unroll
        for (int i = 0; i < 8; i++) cp16(b_dst[i] + ch * BBYTES, b_src[i] + k0);
        asm volatile("cp.async.commit_group;" ::: "memory");
    }

    for (int ch = 0; ch < NCH; ++ch) {
        if (ch + 2 < NCH) {
            int st = (ch + 2) % 3;
            int k0 = (ch + 2) * CHUNK;
#pragma unroll
            for (int i = 0; i < 4; i++) cp16(a_dst[i] + st * ABYTES, a_src[i] + k0);
#pragma unroll
            for (int i = 0; i < 8; i++) cp16(b_dst[i] + st * BBYTES, b_src[i] + k0);
            asm volatile("cp.async.commit_group;" ::: "memory");
            asm volatile("cp.async.wait_group 2;" ::: "memory");
        } else if (ch + 2 == NCH) {
            asm volatile("cp.async.wait_group 1;" ::: "memory");
        } else {
            asm volatile("cp.async.wait_group 0;" ::: "memory");
        }
        __syncthreads();

        const uint32_t Ab = sbase + A_OFF + (ch % 3) * ABYTES;
        const uint32_t Bb = sbase + B_OFF + (ch % 3) * BBYTES;
#pragma unroll
        for (int ks = 0; ks < 4; ks++) {
            uint32_t af[4][4];
#pragma unroll
            for (int ma = 0; ma < 4; ma++) {
                uint32_t cb = (uint32_t)(ks * 32) + a_chi;
                uint32_t addr = Ab + (wm + ma * 16 + a_row) * 128 + (cb ^ cmask);
                asm volatile("ldmatrix.sync.aligned.m8n8.x4.shared.b16 {%0,%1,%2,%3}, [%4];"
                             : "=r"(af[ma][0]), "=r"(af[ma][1]), "=r"(af[ma][2]), "=r"(af[ma][3])
                             : "r"(addr));
            }
            uint32_t bf[4][4];
#pragma unroll
            for (int nb = 0; nb < 4; nb++) {
                uint32_t cb = (uint32_t)(ks * 32) + b_chi;
                uint32_t addr = Bb + (wn + nb * 16 + b_row) * 128 + (cb ^ cmask);
                asm volatile("ldmatrix.sync.aligned.m8n8.x4.shared.b16 {%0,%1,%2,%3}, [%4];"
                             : "=r"(bf[nb][0]), "=r"(bf[nb][1]), "=r"(bf[nb][2]), "=r"(bf[nb][3])
                             : "r"(addr));
            }
#pragma unroll
            for (int ma = 0; ma < 4; ma++)
#pragma unroll
                for (int na = 0; na < 8; na++) {
                    uint32_t b0 = bf[na >> 1][(na & 1) * 2];
                    uint32_t b1 = bf[na >> 1][(na & 1) * 2 + 1];
                    asm volatile(
                        "mma.sync.aligned.m16n8k16.row.col.f32.f16.f16.f32 "
                        "{%0,%1,%2,%3}, {%4,%5,%6,%7}, {%8,%9}, {%0,%1,%2,%3};"
                        : "+f"(acc[ma][na][0]), "+f"(acc[ma][na][1]),
                          "+f"(acc[ma][na][2]), "+f"(acc[ma][na][3])
                        : "r"(af[ma][0]), "r"(af[ma][1]), "r"(af[ma][2]), "r"(af[ma][3]),
                          "r"(b0), "r"(b1));
                }
        }
        __syncthreads();
    }

    // ---- epilogue: pair-shuffle to 4 consecutive cols, one red.v4 per (ma,na) ----
    const bool odd = (tig & 1);
#pragma unroll
    for (int ma = 0; ma < 4; ma++) {
        int r = wm + ma * 16 + gid;
        int rr = odd ? r + 8 : r;
        int tok = s_tok[rr];
        float w = s_w[rr];
        float* orow = out + (size_t)tok * DM + n0;
#pragma unroll
        for (int na = 0; na < 8; na++) {
            float v0 = acc[ma][na][0], v1 = acc[ma][na][1];
            float v2 = acc[ma][na][2], v3 = acc[ma][na][3];
            float u0 = __shfl_xor_sync(0xffffffffu, v0, 1);
            float u1 = __shfl_xor_sync(0xffffffffu, v1, 1);
            float u2 = __shfl_xor_sync(0xffffffffu, v2, 1);
            float u3 = __shfl_xor_sync(0xffffffffu, v3, 1);
            float r0, r1, r2, r3;
            if (!odd) { r0 = v0; r1 = v1; r2 = u0; r3 = u1; }   // row r
            else      { r0 = u2; r1 = u3; r2 = v2; r3 = v3; }   // row r+8
            int j4 = wn + na * 8 + (tig >> 1) * 4;
            if (w != 0.f) {
                float o0 = w * (r0 + s_bias[j4 + 0]);
                float o1 = w * (r1 + s_bias[j4 + 1]);
                float o2 = w * (r2 + s_bias[j4 + 2]);
                float o3 = w * (r3 + s_bias[j4 + 3]);
                asm volatile("red.global.add.v4.f32 [%0], {%1,%2,%3,%4};"
                             :: "l"(orow + j4), "f"(o0), "f"(o1), "f"(o2), "f"(o3)
                             : "memory");
            }
        }
    }
}

extern "C" void kernel_launch(void* const* d_in, const int* in_sizes, int n_in,
                              void* d_out, int out_size) {
    const float* x  = (const float*)d_in[0];
    const float* Wg = (const float*)d_in[1];
    const float* bg = (const float*)d_in[2];
    const float* We = (const float*)d_in[3];
    const float* be = (const float*)d_in[4];
    float* out = (float*)d_out;
    (void)in_sizes; (void)n_in; (void)out_size;

    cudaFuncSetAttribute(moe_gemm_kernel,
                         cudaFuncAttributeMaxDynamicSharedMemorySize, SMEM_TOTAL);

    prep_kernel<<<(NE * DM * DM / 4) / 256, 256>>>((const float4*)We, (float4*)out);
    gate_kernel<<<T_TOK / 8, 256>>>(x, Wg, bg);
    moe_gemm_kernel<<<dim3(T_TOK / BM, DM / BN, NE), 256, SMEM_TOTAL>>>(be, out);
}

// round 5
// speedup vs baseline: 1.6726x; 1.0023x over previous
#include <cuda_runtime.h>
#include <cuda_fp16.h>
#include <cstdint>
#include <cstddef>

#define T_TOK 8192
#define DM    1024
#define NE    8

#define BM 128
#define BN 256
#define CHUNK 64                  // halves of K per chunk (=128 B/row)
#define NCH (DM/CHUNK)            // 16
#define ABYTES (BM*128)           // 16384 per A stage
#define BBYTES (BN*128)           // 32768 per B stage
#define A_OFF 2048
#define B_OFF (A_OFF + 3*ABYTES)              // 51200
#define SMEM_TOTAL (B_OFF + 3*BBYTES)         // 149504

// ---- static device scratch (no allocations allowed) ----
__device__ __align__(16) __half g_x_h[(size_t)T_TOK * DM];     // fp16 x
__device__ __align__(16) __half g_We_h[(size_t)NE * DM * DM];  // fp16 We
__device__ int   g_tok[NE * T_TOK];
__device__ float g_wgt[NE * T_TOK];
__device__ int   g_cnt[NE];

__device__ __forceinline__ void cp16(uint32_t dst, const void* src) {
    asm volatile("cp.async.cg.shared.global [%0], [%1], 16;" :: "r"(dst), "l"(src) : "memory");
}

// ---- kernel 1: fused prep (We->fp16, zero out) + gate (softmax top-2, x->fp16) ----
// blocks [0, 8192): prep; blocks [8192, 9216): gate (8 tokens per block, 1 warp/token)
__global__ void prep_gate_kernel(const float4* __restrict__ We, float4* __restrict__ out,
                                 const float* __restrict__ x, const float* __restrict__ Wg,
                                 const float* __restrict__ bg) {
    const int bid = blockIdx.x;
    if (bid < 8192) {
        int i = bid * blockDim.x + threadIdx.x;   // i < NE*DM*DM/4 == T_TOK*DM/4
        float4 w = We[i];
        __half2 h0 = __floats2half2_rn(w.x, w.y);
        __half2 h1 = __floats2half2_rn(w.z, w.w);
        uint2 pk;
        pk.x = *reinterpret_cast<uint32_t*>(&h0);
        pk.y = *reinterpret_cast<uint32_t*>(&h1);
        reinterpret_cast<uint2*>(g_We_h)[i] = pk;
        out[i] = make_float4(0.f, 0.f, 0.f, 0.f);
        return;
    }

    int t = (bid - 8192) * 8 + (threadIdx.x >> 5);
    int lane = threadIdx.x & 31;
    const float* xr = x + (size_t)t * DM;

    float acc[NE];
#pragma unroll
    for (int e = 0; e < NE; e++) acc[e] = 0.f;

    for (int d = lane; d < DM; d += 32) {
        float v = xr[d];
        g_x_h[(size_t)t * DM + d] = __float2half_rn(v);
#pragma unroll
        for (int e = 0; e < NE; e++) acc[e] = fmaf(v, Wg[e * DM + d], acc[e]);
    }
#pragma unroll
    for (int e = 0; e < NE; e++) {
#pragma unroll
        for (int o = 16; o > 0; o >>= 1) acc[e] += __shfl_xor_sync(0xffffffffu, acc[e], o);
    }

    if (lane == 0) {
        float l[NE];
        float m = -1e30f;
#pragma unroll
        for (int e = 0; e < NE; e++) { l[e] = acc[e] + bg[e]; m = fmaxf(m, l[e]); }
        float p[NE];
        float s = 0.f;
#pragma unroll
        for (int e = 0; e < NE; e++) { p[e] = expf(l[e] - m); s += p[e]; }
        int e0 = 0;
#pragma unroll
        for (int e = 1; e < NE; e++) if (l[e] > l[e0]) e0 = e;
        int e1 = (e0 == 0) ? 1 : 0;
#pragma unroll
        for (int e = 0; e < NE; e++) if (e != e0 && l[e] > l[e1]) e1 = e;
        float inv = 1.f / s;

        int q0 = atomicAdd(&g_cnt[e0], 1);
        g_tok[e0 * T_TOK + q0] = t;
        g_wgt[e0 * T_TOK + q0] = p[e0] * inv;
        int q1 = atomicAdd(&g_cnt[e1], 1);
        g_tok[e1 * T_TOK + q1] = t;
        g_wgt[e1 * T_TOK + q1] = p[e1] * inv;
    }
}

// ---- kernel 2: gathered per-expert fp16 GEMM (mma.sync m16n8k16, fp32 acc) ----
// CTA tile 128x256, 8 warps (2M x 4N), warp tile 64x64, SW128-swizzled smem,
// 3-stage cp.async pipeline, ONE barrier per K-chunk.
__global__ void __launch_bounds__(256, 1)
moe_gemm_kernel(const float* __restrict__ be, float* __restrict__ out) {
    const int e = blockIdx.z;
    const int cnt = g_cnt[e];
    const int m0 = blockIdx.x * BM;
    if (m0 >= cnt) return;

    extern __shared__ __align__(1024) char sm[];
    int*   s_tok  = (int*)sm;              // 128 ints
    float* s_w    = (float*)(sm + 512);    // 128 floats
    float* s_bias = (float*)(sm + 1024);   // 256 floats

    const int tid = threadIdx.x;
    const int n0 = blockIdx.y * BN;

    if (tid < BM) {
        int pos = m0 + tid;
        int tok = 0; float w = 0.f;
        if (pos < cnt) { tok = g_tok[e * T_TOK + pos]; w = g_wgt[e * T_TOK + pos]; }
        s_tok[tid] = tok; s_w[tid] = w;
    }
    s_bias[tid] = be[e * DM + n0 + tid];
    __syncthreads();

    const uint32_t sbase = (uint32_t)__cvta_generic_to_shared(sm);

    // cp.async mapping (per chunk): A = 1024 granules (4/thread), B = 2048 (8/thread)
    const __half* a_src[4];
    uint32_t a_dst[4];
#pragma unroll
    for (int i = 0; i < 4; i++) {
        int slot = i * 256 + tid;
        int row = slot >> 3, q = slot & 7;            // 128 rows x 8 granules
        a_src[i] = g_x_h + (size_t)s_tok[row] * DM + q * 8;
        a_dst[i] = sbase + A_OFF + (uint32_t)(row * 128 + ((q ^ (row & 7)) << 4));
    }
    const __half* b_src[8];
    uint32_t b_dst[8];
#pragma unroll
    for (int i = 0; i < 8; i++) {
        int slot = i * 256 + tid;
        int row = slot >> 3, q = slot & 7;            // 256 rows x 8 granules
        b_src[i] = g_We_h + (size_t)e * DM * DM + (size_t)(n0 + row) * DM + q * 8;
        b_dst[i] = sbase + B_OFF + (uint32_t)(row * 128 + ((q ^ (row & 7)) << 4));
    }

    const int wid = tid >> 5, lane = tid & 31;
    const int wm = (wid & 1) * 64;        // 2 M-warps
    const int wn = (wid >> 1) * 64;       // 4 N-warps
    const int gid = lane >> 2, tig = lane & 3;
    const uint32_t cmask = (uint32_t)((lane & 7) << 4);   // swizzle XOR (bits 4-6)

    const uint32_t a_row = (uint32_t)(lane & 15);
    const uint32_t a_chi = (uint32_t)((lane >> 4) << 4);
    const uint32_t b_row = (uint32_t)(((lane >> 4) << 3) + (lane & 7));
    const uint32_t b_chi = (uint32_t)(((lane >> 3) & 1) << 4);

    float acc[4][8][4];
#pragma unroll
    for (int i0 = 0; i0 < 4; i0++)
#pragma unroll
        for (int i1 = 0; i1 < 8; i1++)
#pragma unroll
            for (int i2 = 0; i2 < 4; i2++) acc[i0][i1][i2] = 0.f;

    // prologue: chunks 0,1 -> stages 0,1
#pragma unroll
    for (int ch = 0; ch < 2; ch++) {
        int k0 = ch * CHUNK;
#pragma unroll
        for (int i = 0; i < 4; i++) cp16(a_dst[i] + ch * ABYTES, a_src[i] + k0);
#pragma unroll
        for (int i = 0; i < 8; i++) cp16(b_dst[i] + ch * BBYTES, b_src[i] + k0);
        asm volatile("cp.async.commit_group;" ::: "memory");
    }

    for (int ch = 0; ch < NCH; ++ch) {
        // ensure group ch complete (own), then barrier publishes all threads' stage ch
        if (ch < NCH - 1) asm volatile("cp.async.wait_group 1;" ::: "memory");
        else              asm volatile("cp.async.wait_group 0;" ::: "memory");
        __syncthreads();
        // after the bar, everyone finished reading stage (ch-1)%3 == (ch+2)%3 -> refill it
        if (ch + 2 < NCH) {
            int st = (ch + 2) % 3;
            int k0 = (ch + 2) * CHUNK;
#pragma unroll
            for (int i = 0; i < 4; i++) cp16(a_dst[i] + st * ABYTES, a_src[i] + k0);
#pragma unroll
            for (int i = 0; i < 8; i++) cp16(b_dst[i] + st * BBYTES, b_src[i] + k0);
            asm volatile("cp.async.commit_group;" ::: "memory");
        }

        const uint32_t Ab = sbase + A_OFF + (ch % 3) * ABYTES;
        const uint32_t Bb = sbase + B_OFF + (ch % 3) * BBYTES;
#pragma unroll
        for (int ks = 0; ks < 4; ks++) {
            uint32_t af[4][4];
#pragma unroll
            for (int ma = 0; ma < 4; ma++) {
                uint32_t cb = (uint32_t)(ks * 32) + a_chi;
                uint32_t addr = Ab + (wm + ma * 16 + a_row) * 128 + (cb ^ cmask);
                asm volatile("ldmatrix.sync.aligned.m8n8.x4.shared.b16 {%0,%1,%2,%3}, [%4];"
                             : "=r"(af[ma][0]), "=r"(af[ma][1]), "=r"(af[ma][2]), "=r"(af[ma][3])
                             : "r"(addr));
            }
            uint32_t bf[4][4];
#pragma unroll
            for (int nb = 0; nb < 4; nb++) {
                uint32_t cb = (uint32_t)(ks * 32) + b_chi;
                uint32_t addr = Bb + (wn + nb * 16 + b_row) * 128 + (cb ^ cmask);
                asm volatile("ldmatrix.sync.aligned.m8n8.x4.shared.b16 {%0,%1,%2,%3}, [%4];"
                             : "=r"(bf[nb][0]), "=r"(bf[nb][1]), "=r"(bf[nb][2]), "=r"(bf[nb][3])
                             : "r"(addr));
            }
#pragma unroll
            for (int ma = 0; ma < 4; ma++)
#pragma unroll
                for (int na = 0; na < 8; na++) {
                    uint32_t b0 = bf[na >> 1][(na & 1) * 2];
                    uint32_t b1 = bf[na >> 1][(na & 1) * 2 + 1];
                    asm volatile(
                        "mma.sync.aligned.m16n8k16.row.col.f32.f16.f16.f32 "
                        "{%0,%1,%2,%3}, {%4,%5,%6,%7}, {%8,%9}, {%0,%1,%2,%3};"
                        : "+f"(acc[ma][na][0]), "+f"(acc[ma][na][1]),
                          "+f"(acc[ma][na][2]), "+f"(acc[ma][na][3])
                        : "r"(af[ma][0]), "r"(af[ma][1]), "r"(af[ma][2]), "r"(af[ma][3]),
                          "r"(b0), "r"(b1));
                }
        }
    }

    // ---- epilogue: pair-shuffle to 4 consecutive cols, one red.v4 per (ma,na) ----
    const bool odd = (tig & 1);
#pragma unroll
    for (int ma = 0; ma < 4; ma++) {
        int r = wm + ma * 16 + gid;
        int rr = odd ? r + 8 : r;
        int tok = s_tok[rr];
        float w = s_w[rr];
        float* orow = out + (size_t)tok * DM + n0;
#pragma unroll
        for (int na = 0; na < 8; na++) {
            float v0 = acc[ma][na][0], v1 = acc[ma][na][1];
            float v2 = acc[ma][na][2], v3 = acc[ma][na][3];
            float u0 = __shfl_xor_sync(0xffffffffu, v0, 1);
            float u1 = __shfl_xor_sync(0xffffffffu, v1, 1);
            float u2 = __shfl_xor_sync(0xffffffffu, v2, 1);
            float u3 = __shfl_xor_sync(0xffffffffu, v3, 1);
            float r0, r1, r2, r3;
            if (!odd) { r0 = v0; r1 = v1; r2 = u0; r3 = u1; }   // row r
            else      { r0 = u2; r1 = u3; r2 = v2; r3 = v3; }   // row r+8
            int j4 = wn + na * 8 + (tig >> 1) * 4;
            if (w != 0.f) {
                float o0 = w * (r0 + s_bias[j4 + 0]);
                float o1 = w * (r1 + s_bias[j4 + 1]);
                float o2 = w * (r2 + s_bias[j4 + 2]);
                float o3 = w * (r3 + s_bias[j4 + 3]);
                asm volatile("red.global.add.v4.f32 [%0], {%1,%2,%3,%4};"
                             :: "l"(orow + j4), "f"(o0), "f"(o1), "f"(o2), "f"(o3)
                             : "memory");
            }
        }
    }
}

extern "C" void kernel_launch(void* const* d_in, const int* in_sizes, int n_in,
                              void* d_out, int out_size) {
    const float* x  = (const float*)d_in[0];
    const float* Wg = (const float*)d_in[1];
    const float* bg = (const float*)d_in[2];
    const float* We = (const float*)d_in[3];
    const float* be = (const float*)d_in[4];
    float* out = (float*)d_out;
    (void)in_sizes; (void)n_in; (void)out_size;

    cudaFuncSetAttribute(moe_gemm_kernel,
                         cudaFuncAttributeMaxDynamicSharedMemorySize, SMEM_TOTAL);

    void* cnt_ptr = nullptr;
    cudaGetSymbolAddress(&cnt_ptr, g_cnt);
    cudaMemsetAsync(cnt_ptr, 0, NE * sizeof(int));

    prep_gate_kernel<<<8192 + T_TOK / 8, 256>>>((const float4*)We, (float4*)out, x, Wg, bg);
    moe_gemm_kernel<<<dim3(T_TOK / BM, DM / BN, NE), 256, SMEM_TOTAL>>>(be, out);
}